// round 5
// baseline (speedup 1.0000x reference)
#include <cuda_runtime.h>
#include <cuda_bf16.h>
#include <math.h>
#include <stdint.h>

#define B_ 32
#define N_ 1024
typedef __nv_bfloat16 bf16;

// ---------------- scratch (static device memory; no runtime alloc) ----------------
__device__ __align__(256) float g_A  [(size_t)B_*N_*N_];     // adjacency fp32
__device__ __align__(256) bf16  g_Lh [(size_t)B_*N_*N_];     // Laplacian hi
__device__ __align__(256) bf16  g_Ll [(size_t)B_*N_*N_];     // Laplacian lo
__device__ __align__(256) bf16  g_Xh [(size_t)B_*N_*512];    // layer input split (ping)
__device__ __align__(256) bf16  g_Xl [(size_t)B_*N_*512];
__device__ __align__(256) bf16  g_Yh [(size_t)B_*N_*512];    // layer input split (pong)
__device__ __align__(256) bf16  g_Yl [(size_t)B_*N_*512];
__device__ __align__(256) bf16  g_Th [(size_t)B_*512*N_];    // transposed operand split
__device__ __align__(256) bf16  g_Tl [(size_t)B_*512*N_];
__device__ __align__(256) float g_x1 [(size_t)B_*N_*512];
__device__ __align__(256) bf16  g_x1h[(size_t)B_*N_*512];
__device__ __align__(256) bf16  g_x1l[(size_t)B_*N_*512];
__device__ __align__(256) bf16  g_x2h[(size_t)B_*N_*512];
__device__ __align__(256) bf16  g_x2l[(size_t)B_*N_*512];
__device__ __align__(256) float g_H1 [(size_t)B_*N_*128];
__device__ __align__(256) float g_H2 [(size_t)B_*N_*512];
__device__ __align__(256) float g_H3 [(size_t)B_*N_*1024];
__device__ __align__(256) bf16  g_Wh [1024*1536];
__device__ __align__(256) bf16  g_Wl [1024*1536];
__device__ float g_sq [B_*N_];
__device__ float g_dis[B_*N_];
__device__ float g_pool[B_*1024];
__device__ float g_f1 [B_*512];
__device__ float g_f2 [B_*128];

// ---------------- PTX helpers ----------------
__device__ __forceinline__ uint32_t smem_u32(const void* p) {
    uint32_t a;
    asm("{ .reg .u64 t; cvta.to.shared.u64 t, %1; cvt.u32.u64 %0, t; }" : "=r"(a) : "l"(p));
    return a;
}
__device__ __forceinline__ void cpa16(uint32_t s, const void* g, int sz) {
    asm volatile("cp.async.cg.shared.global [%0], [%1], 16, %2;" :: "r"(s), "l"(g), "r"(sz));
}
#define CP_COMMIT() asm volatile("cp.async.commit_group;")
#define CP_WAIT1()  asm volatile("cp.async.wait_group 1;")

__device__ __forceinline__ void ldm4(uint32_t* r, uint32_t a) {
    asm volatile("ldmatrix.sync.aligned.m8n8.x4.shared.b16 {%0,%1,%2,%3}, [%4];"
        : "=r"(r[0]), "=r"(r[1]), "=r"(r[2]), "=r"(r[3]) : "r"(a));
}
__device__ __forceinline__ void mma_bf16(float* d, const uint32_t* a, const uint32_t* b) {
    asm volatile("mma.sync.aligned.m16n8k16.row.col.f32.bf16.bf16.f32 "
        "{%0,%1,%2,%3},{%4,%5,%6,%7},{%8,%9},{%0,%1,%2,%3};"
        : "+f"(d[0]), "+f"(d[1]), "+f"(d[2]), "+f"(d[3])
        : "r"(a[0]), "r"(a[1]), "r"(a[2]), "r"(a[3]), "r"(b[0]), "r"(b[1]));
}

// BM=128, BN=256, Kc=32. pitch 80B (64B data + 16B pad; 5r mod 8 permutation
// => conflict-free ldmatrix). 3-stage cp.async pipeline, ONE sync per chunk.
#define PITCH   80
#define TILEA   (128 * PITCH)              /* 10240 */
#define TILEB2  (256 * PITCH)              /* 20480 */
#define OFF_AH  0
#define OFF_AL  TILEA
#define OFF_BH  (2 * TILEA)
#define OFF_BL  (2 * TILEA + TILEB2)
#define STAGE   (2 * TILEA + 2 * TILEB2)   /* 61440 */
#define SMEMSZ  (3 * STAGE)                /* 184320 */

// ---------------- split-bf16 HMMA GEMM ----------------
// C[M,Nv] = sum_seg A_seg[M,Kseg] * B[Nv,K]^T  (A row-major, B K-major [Nv,K])
// MODE 0: plain   MODE 1: __expf(2v - sq_i - sq_j)   MODE 2: 2v - aux   MODE 3: relu(v + bias)
// Outputs: fp32 into Cf (if non-null) and split bf16 into Ch/Cl (if non-null).
template<int MODE>
__global__ __launch_bounds__(512, 1) void gemm_mma(
    const bf16* A0h, const bf16* A0l, const bf16* A1h, const bf16* A1l,
    const bf16* A2h, const bf16* A2l,
    const bf16* Bh, const bf16* Bl,
    float* Cf, bf16* Ch, bf16* Cl,
    int M, int Nv, int K, int Kseg,
    long long sA, long long sB, long long sC,
    const float* sqv, const float* aux, const float* bias)
{
    extern __shared__ char sm[];
    uint32_t sb = smem_u32(sm);
    int tid = threadIdx.x, lane = tid & 31, w = tid >> 5;
    int wm = w & 1, wn = w >> 1;          // 2 x 8 warp grid, warp tile 64x32
    int b = blockIdx.z;
    int iBase = blockIdx.y * 128, jBase = blockIdx.x * 256;

    const bf16* a0h = A0h + (size_t)b * sA;
    const bf16* a0l = A0l + (size_t)b * sA;
    const bf16* a1h = A1h + (size_t)b * sA;
    const bf16* a1l = A1l + (size_t)b * sA;
    const bf16* a2h = A2h + (size_t)b * sA;
    const bf16* a2l = A2l + (size_t)b * sA;
    const bf16* bhp = Bh + (size_t)b * sB;
    const bf16* blp = Bl + (size_t)b * sB;

    float acc[4][4][4];
    #pragma unroll
    for (int i = 0; i < 4; i++)
        #pragma unroll
        for (int j = 0; j < 4; j++)
            #pragma unroll
            for (int k = 0; k < 4; k++) acc[i][j][k] = 0.f;

    int nk = (K + 31) >> 5;
    bool vec = ((K & 31) == 0) && ((Kseg & 31) == 0);

    auto load_vec = [&](int stg, int kc0) {
        uint32_t base = sb + stg * STAGE;
        {   // A limbs: 512 chunks (128 rows x 4) each
            int r = tid >> 2, cc = tid & 3;
            int kg = kc0 + cc * 8;
            int seg = kg / Kseg;
            const bf16* ph = (seg == 0) ? a0h : ((seg == 1) ? a1h : a2h);
            const bf16* pl = (seg == 0) ? a0l : ((seg == 1) ? a1l : a2l);
            size_t offA = (size_t)(iBase + r) * Kseg + (kg - seg * Kseg);
            uint32_t so = base + (uint32_t)(r * PITCH + cc * 16);
            cpa16(so + OFF_AH, ph + offA, 16);
            cpa16(so + OFF_AL, pl + offA, 16);
        }
        #pragma unroll
        for (int jj = 0; jj < 2; jj++) {   // B limbs: 1024 chunks (256 rows x 4) each
            int idx = tid + jj * 512;
            int r = idx >> 2, cc = idx & 3;
            int kg = kc0 + cc * 8;
            int gn = jBase + r;
            int ok = (gn < Nv) ? 16 : 0;
            size_t offB = (size_t)(ok ? gn : 0) * K + kg;
            uint32_t so = base + (uint32_t)(r * PITCH + cc * 16);
            cpa16(so + OFF_BH, bhp + offB, ok);
            cpa16(so + OFF_BL, blp + offB, ok);
        }
    };

    auto compute = [&](int stg) {
        uint32_t base = sb + stg * STAGE;
        #pragma unroll
        for (int ks = 0; ks < 2; ks++) {
            int kk = ks * 16;
            uint32_t ah[4][4], al[4][4];
            #pragma unroll
            for (int i = 0; i < 4; i++) {
                int row = wm * 64 + i * 16 + (lane & 15);
                uint32_t ca = base + (uint32_t)(row * PITCH + ((lane >> 4) * 8 + kk) * 2);
                ldm4(ah[i], ca + OFF_AH);
                ldm4(al[i], ca + OFF_AL);
            }
            uint32_t bh[4][2], bl[4][2];
            #pragma unroll
            for (int jj = 0; jj < 2; jj++) {
                int rn = wn * 32 + jj * 16 + (lane & 7) + ((lane >> 4) & 1) * 8;
                uint32_t cb = base + (uint32_t)(rn * PITCH + (kk + ((lane >> 3) & 1) * 8) * 2);
                uint32_t t4[4];
                ldm4(t4, cb + OFF_BH);
                bh[jj*2][0] = t4[0]; bh[jj*2][1] = t4[1];
                bh[jj*2+1][0] = t4[2]; bh[jj*2+1][1] = t4[3];
                ldm4(t4, cb + OFF_BL);
                bl[jj*2][0] = t4[0]; bl[jj*2][1] = t4[1];
                bl[jj*2+1][0] = t4[2]; bl[jj*2+1][1] = t4[3];
            }
            #pragma unroll
            for (int i = 0; i < 4; i++)
                #pragma unroll
                for (int j = 0; j < 4; j++) {
                    mma_bf16(acc[i][j], ah[i], bh[j]);   // hi*hi
                    mma_bf16(acc[i][j], ah[i], bl[j]);   // hi*lo
                    mma_bf16(acc[i][j], al[i], bh[j]);   // lo*hi
                }
        }
    };

    if (vec) {
        load_vec(0, 0); CP_COMMIT();
        if (nk > 1) load_vec(1, 32);
        CP_COMMIT();
        int cur = 0, tgt = 2;
        for (int i = 0; i < nk; i++) {
            CP_WAIT1();
            __syncthreads();              // stage i ready + everyone done with stage (i+2)%3
            if (i + 2 < nk) load_vec(tgt, (i + 2) * 32);
            CP_COMMIT();
            compute(cur);
            cur = (cur == 2) ? 0 : cur + 1;
            tgt = (tgt == 2) ? 0 : tgt + 1;
        }
    } else {
        // tiny-K path (K <= 32: layer 1 only)
        for (int c = tid; c < STAGE / 16; c += 512) *(uint4*)(sm + (size_t)c * 16) = make_uint4(0,0,0,0);
        __syncthreads();
        for (int idx = tid; idx < 128 * 32; idx += 512) {
            int r = idx >> 5, kc = idx & 31;
            if (kc < K) {
                int seg = kc / Kseg, kkk = kc - seg * Kseg;
                const bf16* ph = (seg == 0) ? a0h : ((seg == 1) ? a1h : a2h);
                const bf16* pl = (seg == 0) ? a0l : ((seg == 1) ? a1l : a2l);
                uint32_t so = (uint32_t)(r * PITCH + kc * 2);
                *(bf16*)(sm + so + OFF_AH) = ph[(size_t)(iBase + r) * Kseg + kkk];
                *(bf16*)(sm + so + OFF_AL) = pl[(size_t)(iBase + r) * Kseg + kkk];
            }
        }
        for (int idx = tid; idx < 256 * 32; idx += 512) {
            int r = idx >> 5, kc = idx & 31;
            int gn = jBase + r;
            if (kc < K && gn < Nv) {
                uint32_t so = (uint32_t)(r * PITCH + kc * 2);
                *(bf16*)(sm + so + OFF_BH) = bhp[(size_t)gn * K + kc];
                *(bf16*)(sm + so + OFF_BL) = blp[(size_t)gn * K + kc];
            }
        }
        __syncthreads();
        compute(0);
    }

    // ---- epilogue ----
    int g = lane >> 2, t = lane & 3;
    float* Cb  = Cf ? Cf + (size_t)b * sC : nullptr;
    bf16* Chb  = Ch ? Ch + (size_t)b * sC : nullptr;
    bf16* Clb  = Cl ? Cl + (size_t)b * sC : nullptr;
    #pragma unroll
    for (int i = 0; i < 4; i++) {
        #pragma unroll
        for (int rr = 0; rr < 2; rr++) {
            int row = iBase + wm * 64 + i * 16 + g + rr * 8;   // M multiple of 128
            float sqi = (MODE == 1) ? sqv[b * N_ + row] : 0.f;
            #pragma unroll
            for (int j = 0; j < 4; j++) {
                int col = jBase + wn * 32 + j * 8 + 2 * t;
                #pragma unroll
                for (int cc = 0; cc < 2; cc++) {
                    int c2 = col + cc;
                    if (c2 < Nv) {
                        float v = acc[i][j][rr * 2 + cc];
                        if (MODE == 1)      v = __expf(2.f * v - sqi - sqv[b * N_ + c2]);
                        else if (MODE == 2) v = 2.f * v - aux[(size_t)b * sC + (size_t)row * Nv + c2];
                        else if (MODE == 3) v = fmaxf(v + bias[c2], 0.f);
                        size_t o = (size_t)row * Nv + c2;
                        if (Cb) Cb[o] = v;
                        if (Chb) {
                            bf16 h = __float2bfloat16(v);
                            Chb[o] = h;
                            Clb[o] = __float2bfloat16(v - __bfloat162float(h));
                        }
                    }
                }
            }
        }
    }
}

// ---------------- conversion / elementwise kernels ----------------
__global__ void split_fp32(const float* __restrict__ X, bf16* __restrict__ H, bf16* __restrict__ L, size_t n) {
    size_t i = ((size_t)blockIdx.x * 256 + threadIdx.x) * 4;
    if (i >= n) return;
    float4 v = *(const float4*)(X + i);
    bf16 hv[4], lv[4];
    float vv[4] = {v.x, v.y, v.z, v.w};
    #pragma unroll
    for (int k = 0; k < 4; k++) {
        bf16 h = __float2bfloat16(vv[k]);
        hv[k] = h;
        lv[k] = __float2bfloat16(vv[k] - __bfloat162float(h));
    }
    *(uint2*)(H + i) = *(uint2*)hv;
    *(uint2*)(L + i) = *(uint2*)lv;
}

__global__ void transpose_split(const float* __restrict__ X, bf16* __restrict__ Th, bf16* __restrict__ Tl, int F) {
    __shared__ float tile[32][33];
    int b = blockIdx.z;
    int n0 = blockIdx.x * 32, f0 = blockIdx.y * 32;
    const float* Xb = X + (size_t)b * N_ * F;
    #pragma unroll
    for (int i = 0; i < 32; i += 8) {
        int nn = n0 + threadIdx.y + i, ff = f0 + threadIdx.x;
        if (ff < F) tile[threadIdx.y + i][threadIdx.x] = Xb[(size_t)nn * F + ff];
    }
    __syncthreads();
    bf16* Thb = Th + (size_t)b * F * N_;
    bf16* Tlb = Tl + (size_t)b * F * N_;
    #pragma unroll
    for (int i = 0; i < 32; i += 8) {
        int ff = f0 + threadIdx.y + i, nn = n0 + threadIdx.x;
        if (ff < F) {
            float v = tile[threadIdx.x][threadIdx.y + i];
            bf16 h = __float2bfloat16(v);
            Thb[(size_t)ff * N_ + nn] = h;
            Tlb[(size_t)ff * N_ + nn] = __float2bfloat16(v - __bfloat162float(h));
        }
    }
}

__global__ void wtrans(const float* __restrict__ W, bf16* __restrict__ Th, bf16* __restrict__ Tl, int Fi, int Fo) {
    int kg = blockIdx.x * 32 + threadIdx.x;
    int o  = blockIdx.y * 8 + threadIdx.y;
    int Kt = 3 * Fi;
    if (kg < Kt && o < Fo) {
        int seg = kg / Fi, kc = kg - seg * Fi;
        float v = W[((size_t)seg * Fi + kc) * Fo + o];
        bf16 h = __float2bfloat16(v);
        Th[(size_t)o * Kt + kg] = h;
        Tl[(size_t)o * Kt + kg] = __float2bfloat16(v - __bfloat162float(h));
    }
}

__global__ void sqnorm(const float* __restrict__ X, float* __restrict__ sq, int F) {
    int row = blockIdx.x * 8 + threadIdx.y;
    const float* r = X + (size_t)row * F;
    float s = 0.f;
    for (int f = threadIdx.x; f < F; f += 32) { float v = r[f]; s += v * v; }
    #pragma unroll
    for (int o = 16; o; o >>= 1) s += __shfl_xor_sync(0xffffffffu, s, o);
    if (threadIdx.x == 0) sq[row] = s;
}

__global__ void rowdeg(const float* __restrict__ A, float* __restrict__ dis) {
    int row = blockIdx.x * 8 + threadIdx.y;
    const float* r = A + (size_t)row * N_;
    float s = 0.f;
    for (int m = threadIdx.x; m < N_; m += 32) s += r[m];
    #pragma unroll
    for (int o = 16; o; o >>= 1) s += __shfl_xor_sync(0xffffffffu, s, o);
    if (threadIdx.x == 0) dis[row] = rsqrtf(s);
}

__global__ void makeL_split(const float* __restrict__ A, const float* __restrict__ dis,
                            bf16* __restrict__ Lh, bf16* __restrict__ Ll) {
    size_t idx = ((size_t)blockIdx.x * 256 + threadIdx.x) * 4;
    int j0 = (int)(idx & (N_ - 1));
    size_t t = idx >> 10;
    int i = (int)(t & (N_ - 1));
    int b = (int)(t >> 10);
    float di = dis[b * N_ + i];
    float4 a = *(const float4*)(A + idx);
    float av[4] = {a.x, a.y, a.z, a.w};
    bf16 hv[4], lv[4];
    #pragma unroll
    for (int k = 0; k < 4; k++) {
        float v = -di * dis[b * N_ + j0 + k] * av[k];
        if (i == j0 + k) v += 1.f;
        bf16 h = __float2bfloat16(v);
        hv[k] = h;
        lv[k] = __float2bfloat16(v - __bfloat162float(h));
    }
    *(uint2*)(Lh + idx) = *(uint2*)hv;
    *(uint2*)(Ll + idx) = *(uint2*)lv;
}

__global__ void maxpool(const float* __restrict__ H, float* __restrict__ out) {
    int f = blockIdx.x * 256 + threadIdx.x;
    int b = blockIdx.y;
    const float* base = H + (size_t)b * N_ * 1024 + f;
    float m = -1e30f;
    for (int n = 0; n < N_; n++) m = fmaxf(m, base[(size_t)n * 1024]);
    out[b * 1024 + f] = m;
}

__global__ void fckernel(const float* __restrict__ in, const float* __restrict__ W,
                         const float* __restrict__ bias, float* __restrict__ out,
                         int K, int Nout, int dorelu) {
    __shared__ float s[1024];
    int b = blockIdx.x;
    for (int i = threadIdx.x; i < K; i += blockDim.x) s[i] = in[(size_t)b * K + i];
    __syncthreads();
    for (int j = threadIdx.x; j < Nout; j += blockDim.x) {
        float acc = bias[j];
        for (int i = 0; i < K; i++) acc = fmaf(s[i], W[(size_t)i * Nout + j], acc);
        if (dorelu) acc = fmaxf(acc, 0.f);
        out[(size_t)b * Nout + j] = acc;
    }
}

// ---------------- host orchestration ----------------
struct Ptrs {
    float *A, *x1, *sq, *dis;
    bf16 *Th, *Tl, *Lh, *Ll, *x1h, *x1l, *x2h, *x2l, *Wh, *Wl;
};

// inH/inL: split of layer input P (already populated). outH/outL: where to write split of H (may be null).
static void conv_layer(const float* P, bf16* inH, bf16* inL, int Fi, int Fo,
                       const float* W, const float* bias,
                       float* H, bf16* outH, bf16* outL, const Ptrs& p)
{
    dim3 tb32(32, 8);

    transpose_split<<<dim3(32, (Fi + 31) / 32, B_), tb32>>>(P, p.Th, p.Tl, Fi);
    sqnorm<<<B_ * N_ / 8, tb32>>>(P, p.sq, Fi);

    // adjacency: A = exp(2*X*X^T - sq_i - sq_j)
    gemm_mma<1><<<dim3(4, 8, B_), 512, SMEMSZ>>>(
        inH, inL, inH, inL, inH, inL, inH, inL,
        p.A, nullptr, nullptr,
        N_, N_, Fi, Fi, (long long)N_ * Fi, (long long)N_ * Fi, (long long)N_ * N_,
        p.sq, nullptr, nullptr);

    rowdeg<<<B_ * N_ / 8, tb32>>>(p.A, p.dis);
    makeL_split<<<(unsigned)((size_t)B_ * N_ * N_ / 1024), 256>>>(p.A, p.dis, p.Lh, p.Ll);

    // x1 = L @ x0 : fp32 (for transpose) + split bf16 (for feature gemm)
    gemm_mma<0><<<dim3((Fi + 255) / 256, 8, B_), 512, SMEMSZ>>>(
        p.Lh, p.Ll, p.Lh, p.Ll, p.Lh, p.Ll, p.Th, p.Tl,
        p.x1, p.x1h, p.x1l,
        N_, Fi, N_, N_, (long long)N_ * N_, (long long)Fi * N_, (long long)N_ * Fi,
        nullptr, nullptr, nullptr);

    transpose_split<<<dim3(32, (Fi + 31) / 32, B_), tb32>>>(p.x1, p.Th, p.Tl, Fi);

    // x2 = 2 L @ x1 - x0 : split bf16 only
    gemm_mma<2><<<dim3((Fi + 255) / 256, 8, B_), 512, SMEMSZ>>>(
        p.Lh, p.Ll, p.Lh, p.Ll, p.Lh, p.Ll, p.Th, p.Tl,
        nullptr, p.x2h, p.x2l,
        N_, Fi, N_, N_, (long long)N_ * N_, (long long)Fi * N_, (long long)N_ * Fi,
        nullptr, P, nullptr);

    wtrans<<<dim3((3 * Fi + 31) / 32, (Fo + 7) / 8), tb32>>>(W, p.Wh, p.Wl, Fi, Fo);

    // H = relu(x0 W0 + x1 W1 + x2 W2 + b); also emit split for next layer
    gemm_mma<3><<<dim3((Fo + 255) / 256, B_ * N_ / 128, 1), 512, SMEMSZ>>>(
        inH, inL, p.x1h, p.x1l, p.x2h, p.x2l, p.Wh, p.Wl,
        H, outH, outL,
        B_ * N_, Fo, 3 * Fi, Fi, 0, 0, 0,
        nullptr, nullptr, bias);
}

extern "C" void kernel_launch(void* const* d_in, const int* in_sizes, int n_in,
                              void* d_out, int out_size) {
    (void)in_sizes; (void)n_in; (void)out_size;
    const float* x     = (const float*)d_in[0];
    const float* W1    = (const float*)d_in[1];
    const float* b1    = (const float*)d_in[2];
    const float* W2    = (const float*)d_in[3];
    const float* b2    = (const float*)d_in[4];
    const float* W3    = (const float*)d_in[5];
    const float* b3    = (const float*)d_in[6];
    const float* fc1_w = (const float*)d_in[7];
    const float* fc1_b = (const float*)d_in[8];
    const float* fc2_w = (const float*)d_in[9];
    const float* fc2_b = (const float*)d_in[10];
    const float* fc3_w = (const float*)d_in[11];
    const float* fc3_b = (const float*)d_in[12];
    float* out = (float*)d_out;

    cudaFuncSetAttribute(gemm_mma<0>, cudaFuncAttributeMaxDynamicSharedMemorySize, SMEMSZ);
    cudaFuncSetAttribute(gemm_mma<1>, cudaFuncAttributeMaxDynamicSharedMemorySize, SMEMSZ);
    cudaFuncSetAttribute(gemm_mma<2>, cudaFuncAttributeMaxDynamicSharedMemorySize, SMEMSZ);
    cudaFuncSetAttribute(gemm_mma<3>, cudaFuncAttributeMaxDynamicSharedMemorySize, SMEMSZ);

    Ptrs p;
    bf16 *Xh, *Xl, *Yh, *Yl;
    float *H1, *H2, *H3, *pool, *f1, *f2;
    cudaGetSymbolAddress((void**)&p.A,   g_A);
    cudaGetSymbolAddress((void**)&p.x1,  g_x1);
    cudaGetSymbolAddress((void**)&p.sq,  g_sq);
    cudaGetSymbolAddress((void**)&p.dis, g_dis);
    cudaGetSymbolAddress((void**)&Xh,    g_Xh);
    cudaGetSymbolAddress((void**)&Xl,    g_Xl);
    cudaGetSymbolAddress((void**)&Yh,    g_Yh);
    cudaGetSymbolAddress((void**)&Yl,    g_Yl);
    cudaGetSymbolAddress((void**)&p.Th,  g_Th);
    cudaGetSymbolAddress((void**)&p.Tl,  g_Tl);
    cudaGetSymbolAddress((void**)&p.Lh,  g_Lh);
    cudaGetSymbolAddress((void**)&p.Ll,  g_Ll);
    cudaGetSymbolAddress((void**)&p.x1h, g_x1h);
    cudaGetSymbolAddress((void**)&p.x1l, g_x1l);
    cudaGetSymbolAddress((void**)&p.x2h, g_x2h);
    cudaGetSymbolAddress((void**)&p.x2l, g_x2l);
    cudaGetSymbolAddress((void**)&p.Wh,  g_Wh);
    cudaGetSymbolAddress((void**)&p.Wl,  g_Wl);
    cudaGetSymbolAddress((void**)&H1,    g_H1);
    cudaGetSymbolAddress((void**)&H2,    g_H2);
    cudaGetSymbolAddress((void**)&H3,    g_H3);
    cudaGetSymbolAddress((void**)&pool,  g_pool);
    cudaGetSymbolAddress((void**)&f1,    g_f1);
    cudaGetSymbolAddress((void**)&f2,    g_f2);

    // layer 1: split the raw input, H1 split -> Y
    split_fp32<<<(unsigned)(((size_t)B_ * N_ * 6 + 1023) / 1024), 256>>>(x, Xh, Xl, (size_t)B_ * N_ * 6);
    conv_layer(x,  Xh, Xl, 6,   128,  W1, b1, H1, Yh, Yl, p);
    // layer 2: input split = Y, H2 split -> X (ping-pong)
    conv_layer(H1, Yh, Yl, 128, 512,  W2, b2, H2, Xh, Xl, p);
    // layer 3: input split = X, no H split needed
    conv_layer(H2, Xh, Xl, 512, 1024, W3, b3, H3, nullptr, nullptr, p);

    maxpool<<<dim3(4, B_), 256>>>(H3, pool);
    fckernel<<<B_, 256>>>(pool, fc1_w, fc1_b, f1, 1024, 512, 1);
    fckernel<<<B_, 256>>>(f1,   fc2_w, fc2_b, f2, 512, 128, 1);
    fckernel<<<B_, 256>>>(f2,   fc3_w, fc3_b, out, 128, 40, 0);
}

// round 7
// speedup vs baseline: 1.1465x; 1.1465x over previous
#include <cuda_runtime.h>
#include <cuda_bf16.h>
#include <math.h>
#include <stdint.h>

#define B_ 32
#define N_ 1024
typedef __nv_bfloat16 bf16;

// ---------------- scratch (static device memory; no runtime alloc) ----------------
__device__ __align__(256) float g_A  [(size_t)B_*N_*N_];     // adjacency fp32
__device__ __align__(256) bf16  g_Lh [(size_t)B_*N_*N_];     // Laplacian hi
__device__ __align__(256) bf16  g_Ll [(size_t)B_*N_*N_];     // Laplacian lo
__device__ __align__(256) bf16  g_Xh [(size_t)B_*N_*512];    // layer input split (ping)
__device__ __align__(256) bf16  g_Xl [(size_t)B_*N_*512];
__device__ __align__(256) bf16  g_Yh [(size_t)B_*N_*512];    // layer input split (pong)
__device__ __align__(256) bf16  g_Yl [(size_t)B_*N_*512];
__device__ __align__(256) bf16  g_Th [(size_t)B_*512*N_];    // transposed operand split
__device__ __align__(256) bf16  g_Tl [(size_t)B_*512*N_];
__device__ __align__(256) float g_x1 [(size_t)B_*N_*512];
__device__ __align__(256) bf16  g_x1h[(size_t)B_*N_*512];
__device__ __align__(256) bf16  g_x1l[(size_t)B_*N_*512];
__device__ __align__(256) bf16  g_x2h[(size_t)B_*N_*512];
__device__ __align__(256) bf16  g_x2l[(size_t)B_*N_*512];
__device__ __align__(256) float g_H1 [(size_t)B_*N_*128];
__device__ __align__(256) float g_H2 [(size_t)B_*N_*512];
__device__ __align__(256) float g_H3 [(size_t)B_*N_*1024];
__device__ __align__(256) bf16  g_Wh [1024*1536];
__device__ __align__(256) bf16  g_Wl [1024*1536];
__device__ float g_sq [B_*N_];
__device__ float g_dis[B_*N_];
__device__ float g_pool[B_*1024];
__device__ float g_f1 [B_*512];
__device__ float g_f2 [B_*128];

// ---------------- PTX helpers ----------------
__device__ __forceinline__ uint32_t smem_u32(const void* p) {
    uint32_t a;
    asm("{ .reg .u64 t; cvta.to.shared.u64 t, %1; cvt.u32.u64 %0, t; }" : "=r"(a) : "l"(p));
    return a;
}
__device__ __forceinline__ void cpa16(uint32_t s, const void* g, int sz) {
    asm volatile("cp.async.cg.shared.global [%0], [%1], 16, %2;" :: "r"(s), "l"(g), "r"(sz));
}
#define CP_COMMIT() asm volatile("cp.async.commit_group;")
#define CP_WAIT0()  asm volatile("cp.async.wait_group 0;")
#define CP_WAIT1()  asm volatile("cp.async.wait_group 1;")

__device__ __forceinline__ void ldm4(uint32_t* r, uint32_t a) {
    asm volatile("ldmatrix.sync.aligned.m8n8.x4.shared.b16 {%0,%1,%2,%3}, [%4];"
        : "=r"(r[0]), "=r"(r[1]), "=r"(r[2]), "=r"(r[3]) : "r"(a));
}
__device__ __forceinline__ void mma_bf16(float* d, const uint32_t* a, const uint32_t* b) {
    asm volatile("mma.sync.aligned.m16n8k16.row.col.f32.bf16.bf16.f32 "
        "{%0,%1,%2,%3},{%4,%5,%6,%7},{%8,%9},{%0,%1,%2,%3};"
        : "+f"(d[0]), "+f"(d[1]), "+f"(d[2]), "+f"(d[3])
        : "r"(a[0]), "r"(a[1]), "r"(a[2]), "r"(a[3]), "r"(b[0]), "r"(b[1]));
}

// smem tile: 128 rows x 32 bf16 cols, pitch 80B (64B data + 16B pad; 5r mod 8 permutation
// => conflict-free ldmatrix). K-chunk 32, double-buffered => 80KB => 2 CTAs/SM.
#define PITCH  80
#define TILEB  (128 * PITCH)     /* 10240 bytes per operand-limb tile */
#define STAGE  (4 * TILEB)       /* Ah | Al | Bh | Bl = 40960 */
#define SMEMSZ (2 * STAGE)       /* double buffered = 81920 */

// ---------------- split-bf16 HMMA GEMM (round-4 mainloop + fused split epilogue) ------------
// C[M,Nv] = sum_seg A_seg[M,Kseg] * B[Nv,K]^T  (A row-major, B K-major [Nv,K])
// MODE 0: plain   MODE 1: __expf(2v - sq_i - sq_j)   MODE 2: 2v - aux   MODE 3: relu(v + bias)
// Writes fp32 to Cf (if non-null) and split bf16 to Ch/Cl (if non-null).
template<int MODE>
__global__ __launch_bounds__(256, 2) void gemm_mma(
    const bf16* A0h, const bf16* A0l, const bf16* A1h, const bf16* A1l,
    const bf16* A2h, const bf16* A2l,
    const bf16* Bh, const bf16* Bl,
    float* Cf, bf16* Ch, bf16* Cl,
    int M, int Nv, int K, int Kseg,
    long long sA, long long sB, long long sC,
    const float* sqv, const float* aux, const float* bias)
{
    extern __shared__ char sm[];
    uint32_t sb = smem_u32(sm);
    int tid = threadIdx.x, lane = tid & 31, w = tid >> 5;
    int wm = w & 1, wn = w >> 1;          // 2 x 4 warp grid, warp tile 64x32
    int b = blockIdx.z;
    int iBase = blockIdx.y * 128, jBase = blockIdx.x * 128;

    const bf16* a0h = A0h + (size_t)b * sA;
    const bf16* a0l = A0l + (size_t)b * sA;
    const bf16* a1h = A1h + (size_t)b * sA;
    const bf16* a1l = A1l + (size_t)b * sA;
    const bf16* a2h = A2h + (size_t)b * sA;
    const bf16* a2l = A2l + (size_t)b * sA;
    const bf16* bhp = Bh + (size_t)b * sB;
    const bf16* blp = Bl + (size_t)b * sB;

    float acc[4][4][4];
    #pragma unroll
    for (int i = 0; i < 4; i++)
        #pragma unroll
        for (int j = 0; j < 4; j++)
            #pragma unroll
            for (int k = 0; k < 4; k++) acc[i][j][k] = 0.f;

    int nk = (K + 31) >> 5;
    bool vec = ((K & 31) == 0) && ((Kseg & 31) == 0);

    auto load_vec = [&](int stg, int kc0) {
        uint32_t base = sb + stg * STAGE;
        #pragma unroll
        for (int jj = 0; jj < 2; jj++) {
            int c = tid + jj * 256;            // 512 (row, chunk) pairs: 128 rows x 4
            int r = c >> 2, cc = c & 3;
            int kg = kc0 + cc * 8;
            uint32_t so = base + (uint32_t)(r * PITCH + cc * 16);
            int seg = kg / Kseg;
            const bf16* ph = (seg == 0) ? a0h : ((seg == 1) ? a1h : a2h);
            const bf16* pl = (seg == 0) ? a0l : ((seg == 1) ? a1l : a2l);
            size_t offA = (size_t)(iBase + r) * Kseg + (kg - seg * Kseg);
            cpa16(so,             ph + offA, 16);
            cpa16(so + TILEB,     pl + offA, 16);
            int gn = jBase + r;
            int ok = (gn < Nv) ? 16 : 0;
            size_t offB = (size_t)(ok ? gn : 0) * K + kg;
            cpa16(so + 2 * TILEB, bhp + offB, ok);
            cpa16(so + 3 * TILEB, blp + offB, ok);
        }
    };

    auto compute = [&](int stg) {
        uint32_t base = sb + stg * STAGE;
        #pragma unroll
        for (int ks = 0; ks < 2; ks++) {
            int kk = ks * 16;
            uint32_t ah[4][4], al[4][4];
            #pragma unroll
            for (int i = 0; i < 4; i++) {
                int row = wm * 64 + i * 16 + (lane & 15);
                uint32_t ca = base + (uint32_t)(row * PITCH + ((lane >> 4) * 8 + kk) * 2);
                ldm4(ah[i], ca);
                ldm4(al[i], ca + TILEB);
            }
            uint32_t bh[4][2], bl[4][2];
            #pragma unroll
            for (int jj = 0; jj < 2; jj++) {
                int rn = wn * 32 + jj * 16 + (lane & 7) + ((lane >> 4) & 1) * 8;
                uint32_t cb = base + 2 * TILEB +
                              (uint32_t)(rn * PITCH + (kk + ((lane >> 3) & 1) * 8) * 2);
                uint32_t t4[4];
                ldm4(t4, cb);
                bh[jj*2][0] = t4[0]; bh[jj*2][1] = t4[1];
                bh[jj*2+1][0] = t4[2]; bh[jj*2+1][1] = t4[3];
                ldm4(t4, cb + TILEB);
                bl[jj*2][0] = t4[0]; bl[jj*2][1] = t4[1];
                bl[jj*2+1][0] = t4[2]; bl[jj*2+1][1] = t4[3];
            }
            #pragma unroll
            for (int i = 0; i < 4; i++)
                #pragma unroll
                for (int j = 0; j < 4; j++) {
                    mma_bf16(acc[i][j], ah[i], bh[j]);   // hi*hi
                    mma_bf16(acc[i][j], ah[i], bl[j]);   // hi*lo
                    mma_bf16(acc[i][j], al[i], bh[j]);   // lo*hi
                }
        }
    };

    if (vec) {
        load_vec(0, 0); CP_COMMIT();
        for (int i = 0; i < nk; i++) {
            if (i + 1 < nk) { load_vec((i + 1) & 1, (i + 1) * 32); CP_COMMIT(); CP_WAIT1(); }
            else            { CP_WAIT0(); }
            __syncthreads();
            compute(i & 1);
            __syncthreads();
        }
    } else {
        // tiny-K path (layer 1 only: K=6 or K=18)
        for (int c = tid; c < STAGE / 16; c += 256) *(uint4*)(sm + (size_t)c * 16) = make_uint4(0,0,0,0);
        __syncthreads();
        for (int i = 0; i < nk; i++) {
            for (int idx = tid; idx < 128 * 32; idx += 256) {
                int r = idx >> 5, kc = idx & 31;
                int kg = i * 32 + kc;
                uint32_t so = (uint32_t)(r * PITCH + kc * 2);
                if (kg < K) {
                    int seg = kg / Kseg, kkk = kg - seg * Kseg;
                    const bf16* ph = (seg == 0) ? a0h : ((seg == 1) ? a1h : a2h);
                    const bf16* pl = (seg == 0) ? a0l : ((seg == 1) ? a1l : a2l);
                    *(bf16*)(sm + so)          = ph[(size_t)(iBase + r) * Kseg + kkk];
                    *(bf16*)(sm + so + TILEB)  = pl[(size_t)(iBase + r) * Kseg + kkk];
                    int gn = jBase + r;
                    if (gn < Nv) {
                        *(bf16*)(sm + so + 2 * TILEB) = bhp[(size_t)gn * K + kg];
                        *(bf16*)(sm + so + 3 * TILEB) = blp[(size_t)gn * K + kg];
                    }
                }
            }
            __syncthreads();
            compute(0);
            __syncthreads();
            if (i + 1 < nk) {
                for (int c = tid; c < STAGE / 16; c += 256) *(uint4*)(sm + (size_t)c * 16) = make_uint4(0,0,0,0);
                __syncthreads();
            }
        }
    }

    // ---- epilogue (fused: fp32 and/or split-bf16 outputs) ----
    int g = lane >> 2, t = lane & 3;
    float* Cb  = Cf ? Cf + (size_t)b * sC : nullptr;
    bf16* Chb  = Ch ? Ch + (size_t)b * sC : nullptr;
    bf16* Clb  = Cl ? Cl + (size_t)b * sC : nullptr;
    #pragma unroll
    for (int i = 0; i < 4; i++) {
        #pragma unroll
        for (int rr = 0; rr < 2; rr++) {
            int row = iBase + wm * 64 + i * 16 + g + rr * 8;   // M is multiple of 128
            float sqi = (MODE == 1) ? sqv[b * N_ + row] : 0.f;
            #pragma unroll
            for (int j = 0; j < 4; j++) {
                int col = jBase + wn * 32 + j * 8 + 2 * t;
                #pragma unroll
                for (int cc = 0; cc < 2; cc++) {
                    int c2 = col + cc;
                    if (c2 < Nv) {
                        float v = acc[i][j][rr * 2 + cc];
                        if (MODE == 1)      v = __expf(2.f * v - sqi - sqv[b * N_ + c2]);
                        else if (MODE == 2) v = 2.f * v - aux[(size_t)b * sC + (size_t)row * Nv + c2];
                        else if (MODE == 3) v = fmaxf(v + bias[c2], 0.f);
                        size_t o = (size_t)row * Nv + c2;
                        if (Cb) Cb[o] = v;
                        if (Chb) {
                            bf16 h = __float2bfloat16(v);
                            Chb[o] = h;
                            Clb[o] = __float2bfloat16(v - __bfloat162float(h));
                        }
                    }
                }
            }
        }
    }
}

// ---------------- conversion / elementwise kernels ----------------
__global__ void split_fp32(const float* __restrict__ X, bf16* __restrict__ H, bf16* __restrict__ L, size_t n) {
    size_t i = ((size_t)blockIdx.x * 256 + threadIdx.x) * 4;
    if (i >= n) return;
    float4 v = *(const float4*)(X + i);
    bf16 hv[4], lv[4];
    float vv[4] = {v.x, v.y, v.z, v.w};
    #pragma unroll
    for (int k = 0; k < 4; k++) {
        bf16 h = __float2bfloat16(vv[k]);
        hv[k] = h;
        lv[k] = __float2bfloat16(vv[k] - __bfloat162float(h));
    }
    *(uint2*)(H + i) = *(uint2*)hv;
    *(uint2*)(L + i) = *(uint2*)lv;
}

__global__ void transpose_split(const float* __restrict__ X, bf16* __restrict__ Th, bf16* __restrict__ Tl, int F) {
    __shared__ float tile[32][33];
    int b = blockIdx.z;
    int n0 = blockIdx.x * 32, f0 = blockIdx.y * 32;
    const float* Xb = X + (size_t)b * N_ * F;
    #pragma unroll
    for (int i = 0; i < 32; i += 8) {
        int nn = n0 + threadIdx.y + i, ff = f0 + threadIdx.x;
        if (ff < F) tile[threadIdx.y + i][threadIdx.x] = Xb[(size_t)nn * F + ff];
    }
    __syncthreads();
    bf16* Thb = Th + (size_t)b * F * N_;
    bf16* Tlb = Tl + (size_t)b * F * N_;
    #pragma unroll
    for (int i = 0; i < 32; i += 8) {
        int ff = f0 + threadIdx.y + i, nn = n0 + threadIdx.x;
        if (ff < F) {
            float v = tile[threadIdx.x][threadIdx.y + i];
            bf16 h = __float2bfloat16(v);
            Thb[(size_t)ff * N_ + nn] = h;
            Tlb[(size_t)ff * N_ + nn] = __float2bfloat16(v - __bfloat162float(h));
        }
    }
}

__global__ void wtrans(const float* __restrict__ W, bf16* __restrict__ Th, bf16* __restrict__ Tl, int Fi, int Fo) {
    int kg = blockIdx.x * 32 + threadIdx.x;
    int o  = blockIdx.y * 8 + threadIdx.y;
    int Kt = 3 * Fi;
    if (kg < Kt && o < Fo) {
        int seg = kg / Fi, kc = kg - seg * Fi;
        float v = W[((size_t)seg * Fi + kc) * Fo + o];
        bf16 h = __float2bfloat16(v);
        Th[(size_t)o * Kt + kg] = h;
        Tl[(size_t)o * Kt + kg] = __float2bfloat16(v - __bfloat162float(h));
    }
}

__global__ void sqnorm(const float* __restrict__ X, float* __restrict__ sq, int F) {
    int row = blockIdx.x * 8 + threadIdx.y;
    const float* r = X + (size_t)row * F;
    float s = 0.f;
    for (int f = threadIdx.x; f < F; f += 32) { float v = r[f]; s += v * v; }
    #pragma unroll
    for (int o = 16; o; o >>= 1) s += __shfl_xor_sync(0xffffffffu, s, o);
    if (threadIdx.x == 0) sq[row] = s;
}

__global__ void rowdeg(const float* __restrict__ A, float* __restrict__ dis) {
    int row = blockIdx.x * 8 + threadIdx.y;
    const float* r = A + (size_t)row * N_;
    float s = 0.f;
    for (int m = threadIdx.x; m < N_; m += 32) s += r[m];
    #pragma unroll
    for (int o = 16; o; o >>= 1) s += __shfl_xor_sync(0xffffffffu, s, o);
    if (threadIdx.x == 0) dis[row] = rsqrtf(s);
}

__global__ void makeL_split(const float* __restrict__ A, const float* __restrict__ dis,
                            bf16* __restrict__ Lh, bf16* __restrict__ Ll) {
    size_t idx = ((size_t)blockIdx.x * 256 + threadIdx.x) * 4;
    int j0 = (int)(idx & (N_ - 1));
    size_t t = idx >> 10;
    int i = (int)(t & (N_ - 1));
    int b = (int)(t >> 10);
    float di = dis[b * N_ + i];
    float4 a = *(const float4*)(A + idx);
    float av[4] = {a.x, a.y, a.z, a.w};
    bf16 hv[4], lv[4];
    #pragma unroll
    for (int k = 0; k < 4; k++) {
        float v = -di * dis[b * N_ + j0 + k] * av[k];
        if (i == j0 + k) v += 1.f;
        bf16 h = __float2bfloat16(v);
        hv[k] = h;
        lv[k] = __float2bfloat16(v - __bfloat162float(h));
    }
    *(uint2*)(Lh + idx) = *(uint2*)hv;
    *(uint2*)(Ll + idx) = *(uint2*)lv;
}

__global__ void maxpool(const float* __restrict__ H, float* __restrict__ out) {
    int f = blockIdx.x * 256 + threadIdx.x;
    int b = blockIdx.y;
    const float* base = H + (size_t)b * N_ * 1024 + f;
    float m = -1e30f;
    for (int n = 0; n < N_; n++) m = fmaxf(m, base[(size_t)n * 1024]);
    out[b * 1024 + f] = m;
}

__global__ void fckernel(const float* __restrict__ in, const float* __restrict__ W,
                         const float* __restrict__ bias, float* __restrict__ out,
                         int K, int Nout, int dorelu) {
    __shared__ float s[1024];
    int b = blockIdx.x;
    for (int i = threadIdx.x; i < K; i += blockDim.x) s[i] = in[(size_t)b * K + i];
    __syncthreads();
    for (int j = threadIdx.x; j < Nout; j += blockDim.x) {
        float acc = bias[j];
        for (int i = 0; i < K; i++) acc = fmaf(s[i], W[(size_t)i * Nout + j], acc);
        if (dorelu) acc = fmaxf(acc, 0.f);
        out[(size_t)b * Nout + j] = acc;
    }
}

// ---------------- host orchestration ----------------
struct Ptrs {
    float *A, *x1, *sq, *dis;
    bf16 *Th, *Tl, *Lh, *Ll, *x1h, *x1l, *x2h, *x2l, *Wh, *Wl;
};

// inH/inL: split of layer input P (already populated). outH/outL: split of H for next layer (may be null).
static void conv_layer(const float* P, bf16* inH, bf16* inL, int Fi, int Fo,
                       const float* W, const float* bias,
                       float* H, bf16* outH, bf16* outL, const Ptrs& p)
{
    dim3 tb32(32, 8);

    transpose_split<<<dim3(32, (Fi + 31) / 32, B_), tb32>>>(P, p.Th, p.Tl, Fi);
    sqnorm<<<B_ * N_ / 8, tb32>>>(P, p.sq, Fi);

    // adjacency: A = exp(2*X*X^T - sq_i - sq_j)
    gemm_mma<1><<<dim3(8, 8, B_), 256, SMEMSZ>>>(
        inH, inL, inH, inL, inH, inL, inH, inL,
        p.A, nullptr, nullptr,
        N_, N_, Fi, Fi, (long long)N_ * Fi, (long long)N_ * Fi, (long long)N_ * N_,
        p.sq, nullptr, nullptr);

    rowdeg<<<B_ * N_ / 8, tb32>>>(p.A, p.dis);
    makeL_split<<<(unsigned)((size_t)B_ * N_ * N_ / 1024), 256>>>(p.A, p.dis, p.Lh, p.Ll);

    // x1 = L @ x0 : fp32 (for transpose) + split bf16 (for feature gemm)
    gemm_mma<0><<<dim3((Fi + 127) / 128, 8, B_), 256, SMEMSZ>>>(
        p.Lh, p.Ll, p.Lh, p.Ll, p.Lh, p.Ll, p.Th, p.Tl,
        p.x1, p.x1h, p.x1l,
        N_, Fi, N_, N_, (long long)N_ * N_, (long long)Fi * N_, (long long)N_ * Fi,
        nullptr, nullptr, nullptr);

    transpose_split<<<dim3(32, (Fi + 31) / 32, B_), tb32>>>(p.x1, p.Th, p.Tl, Fi);

    // x2 = 2 L @ x1 - x0 : split bf16 only (no fp32 materialization)
    gemm_mma<2><<<dim3((Fi + 127) / 128, 8, B_), 256, SMEMSZ>>>(
        p.Lh, p.Ll, p.Lh, p.Ll, p.Lh, p.Ll, p.Th, p.Tl,
        nullptr, p.x2h, p.x2l,
        N_, Fi, N_, N_, (long long)N_ * N_, (long long)Fi * N_, (long long)N_ * Fi,
        nullptr, P, nullptr);

    wtrans<<<dim3((3 * Fi + 31) / 32, (Fo + 7) / 8), tb32>>>(W, p.Wh, p.Wl, Fi, Fo);

    // H = relu(x0 W0 + x1 W1 + x2 W2 + b); also emit next layer's split
    gemm_mma<3><<<dim3((Fo + 127) / 128, B_ * N_ / 128, 1), 256, SMEMSZ>>>(
        inH, inL, p.x1h, p.x1l, p.x2h, p.x2l, p.Wh, p.Wl,
        H, outH, outL,
        B_ * N_, Fo, 3 * Fi, Fi, 0, 0, 0,
        nullptr, nullptr, bias);
}

extern "C" void kernel_launch(void* const* d_in, const int* in_sizes, int n_in,
                              void* d_out, int out_size) {
    (void)in_sizes; (void)n_in; (void)out_size;
    const float* x     = (const float*)d_in[0];
    const float* W1    = (const float*)d_in[1];
    const float* b1    = (const float*)d_in[2];
    const float* W2    = (const float*)d_in[3];
    const float* b2    = (const float*)d_in[4];
    const float* W3    = (const float*)d_in[5];
    const float* b3    = (const float*)d_in[6];
    const float* fc1_w = (const float*)d_in[7];
    const float* fc1_b = (const float*)d_in[8];
    const float* fc2_w = (const float*)d_in[9];
    const float* fc2_b = (const float*)d_in[10];
    const float* fc3_w = (const float*)d_in[11];
    const float* fc3_b = (const float*)d_in[12];
    float* out = (float*)d_out;

    cudaFuncSetAttribute(gemm_mma<0>, cudaFuncAttributeMaxDynamicSharedMemorySize, SMEMSZ);
    cudaFuncSetAttribute(gemm_mma<1>, cudaFuncAttributeMaxDynamicSharedMemorySize, SMEMSZ);
    cudaFuncSetAttribute(gemm_mma<2>, cudaFuncAttributeMaxDynamicSharedMemorySize, SMEMSZ);
    cudaFuncSetAttribute(gemm_mma<3>, cudaFuncAttributeMaxDynamicSharedMemorySize, SMEMSZ);

    Ptrs p;
    bf16 *Xh, *Xl, *Yh, *Yl;
    float *H1, *H2, *H3, *pool, *f1, *f2;
    cudaGetSymbolAddress((void**)&p.A,   g_A);
    cudaGetSymbolAddress((void**)&p.x1,  g_x1);
    cudaGetSymbolAddress((void**)&p.sq,  g_sq);
    cudaGetSymbolAddress((void**)&p.dis, g_dis);
    cudaGetSymbolAddress((void**)&Xh,    g_Xh);
    cudaGetSymbolAddress((void**)&Xl,    g_Xl);
    cudaGetSymbolAddress((void**)&Yh,    g_Yh);
    cudaGetSymbolAddress((void**)&Yl,    g_Yl);
    cudaGetSymbolAddress((void**)&p.Th,  g_Th);
    cudaGetSymbolAddress((void**)&p.Tl,  g_Tl);
    cudaGetSymbolAddress((void**)&p.Lh,  g_Lh);
    cudaGetSymbolAddress((void**)&p.Ll,  g_Ll);
    cudaGetSymbolAddress((void**)&p.x1h, g_x1h);
    cudaGetSymbolAddress((void**)&p.x1l, g_x1l);
    cudaGetSymbolAddress((void**)&p.x2h, g_x2h);
    cudaGetSymbolAddress((void**)&p.x2l, g_x2l);
    cudaGetSymbolAddress((void**)&p.Wh,  g_Wh);
    cudaGetSymbolAddress((void**)&p.Wl,  g_Wl);
    cudaGetSymbolAddress((void**)&H1,    g_H1);
    cudaGetSymbolAddress((void**)&H2,    g_H2);
    cudaGetSymbolAddress((void**)&H3,    g_H3);
    cudaGetSymbolAddress((void**)&pool,  g_pool);
    cudaGetSymbolAddress((void**)&f1,    g_f1);
    cudaGetSymbolAddress((void**)&f2,    g_f2);

    // layer 1: split the raw input, H1 split -> Y
    split_fp32<<<(unsigned)(((size_t)B_ * N_ * 6 + 1023) / 1024), 256>>>(x, Xh, Xl, (size_t)B_ * N_ * 6);
    conv_layer(x,  Xh, Xl, 6,   128,  W1, b1, H1, Yh, Yl, p);
    // layer 2: input split = Y, H2 split -> X (ping-pong)
    conv_layer(H1, Yh, Yl, 128, 512,  W2, b2, H2, Xh, Xl, p);
    // layer 3: input split = X, no H split needed
    conv_layer(H2, Xh, Xl, 512, 1024, W3, b3, H3, nullptr, nullptr, p);

    maxpool<<<dim3(4, B_), 256>>>(H3, pool);
    fckernel<<<B_, 256>>>(pool, fc1_w, fc1_b, f1, 1024, 512, 1);
    fckernel<<<B_, 256>>>(f1,   fc2_w, fc2_b, f2, 512, 128, 1);
    fckernel<<<B_, 256>>>(f2,   fc3_w, fc3_b, out, 128, 40, 0);
}